// round 10
// baseline (speedup 1.0000x reference)
#include <cuda_runtime.h>
#include <cstdint>

// adder2d via SIMD SAD: out[b,f,l] = -(1/4096) * sum_{cp,kh,kw} vabsdiff2(xq, wq)
// xq/wq are s16 quantized (scale 4096), channel PAIRS packed in SIMD lanes
// (lanes are reduction-dim, summed by the .add form into scalar s32 acc -> exact).
// Grid: 16 fgroups(8 filters) x 16 batches x 4 chunks(16 cpairs) = 1024 CTAs.
// CTA 224 thr: t<112 -> filters fbase+0..3, t>=112 -> fbase+4..7; 7 pixels each.

#define BATCH 16
#define CIN   128
#define HW    28
#define LSP   784
#define FOUT  128
#define NT    224
#define NCP   64          // channel pairs total
#define CPP   16          // channel pairs per CTA
#define NCHQ  4
#define SROW  36          // tile row stride (u32)
#define TROWS 30
#define QS    4096.0f

typedef unsigned int u32;

__device__ u32 g_xq[BATCH * NCP * LSP];   // [b][cp][l]      (s16 c_even, s16 c_odd)
__device__ u32 g_wq[NCP * 9 * FOUT];      // [(cp*9+kk)][f]  (s16 c_even, s16 c_odd)

// acc += |x.h0 - w.h0| + |x.h1 - w.h1|   (one SIMD SAD instruction)
__device__ __forceinline__ void sad2(u32& acc, u32 xp, u32 wp) {
    asm("vabsdiff2.s32.s32.s32.add %0, %1, %2, %0;" : "+r"(acc) : "r"(xp), "r"(wp));
}

__device__ __forceinline__ u32 pack_q(float a, float b) {
    int v0 = __float2int_rn(a * QS);
    int v1 = __float2int_rn(b * QS);
    return ((u32)v0 & 0xFFFFu) | ((u32)v1 << 16);
}

__global__ void zero_out_kernel(float4* o) {
    o[(size_t)blockIdx.x * 1024 + threadIdx.x] = make_float4(0.f, 0.f, 0.f, 0.f);
}

__global__ void prep_x_kernel(const float* __restrict__ x) {
    int i  = blockIdx.x * 1024 + threadIdx.x;      // over 16*64*784 = 802816
    int l  = i % LSP;
    int cp = (i / LSP) & (NCP - 1);
    int b  = i / (LSP * NCP);
    const float* xp = x + ((size_t)b * CIN + 2 * cp) * LSP + l;
    g_xq[i] = pack_q(xp[0], xp[LSP]);
}

__global__ void prep_w_kernel(const float* __restrict__ Wt) {
    int i = blockIdx.x * 256 + threadIdx.x;        // over 64*9*128 = 73728
    int f  = i & (FOUT - 1);
    int ck = i >> 7;                               // cp*9 + kk
    int cp = ck / 9, kk = ck - cp * 9;
    const float* wp = Wt + ((size_t)f * CIN + 2 * cp) * 9 + kk;
    g_wq[i] = pack_q(wp[0], wp[9]);
}

__global__ __launch_bounds__(NT, 5)
void adder2d_kernel(float* __restrict__ out) {
    __shared__ u32 xs[2][TROWS * SROW];   // channel-pair tiles, 8640 B
    __shared__ u32 ws[CPP * 9 * 8];       // [(cpl*9+kk)][f0..7], 4608 B

    const int b     = blockIdx.y;
    const int fbase = blockIdx.x * 8;     // 8 filters per CTA
    const int cq    = blockIdx.z;         // 16-cpair chunk
    const int t     = threadIdx.x;
    const int tl    = (t < 112) ? t : (t - 112);
    const int g     = (t < 112) ? 0 : 4;  // filter sub-base
    const int h     = tl >> 2;
    const int q     = tl & 3;

    // zero both tiles (halo stays zero)
    for (int i = t; i < 2 * TROWS * SROW; i += NT)
        (&xs[0][0])[i] = 0u;

    // stage W: 16 cpairs x 9 kk x 8 filters (coalesced from g_wq)
    {
        const u32* wp = g_wq + (size_t)(cq * CPP * 9) * FOUT + fbase;
        for (int i = t; i < CPP * 9 * 8; i += NT) {
            int fl = i & 7;
            int ck = i >> 3;
            ws[i] = wp[(size_t)ck * FOUT + fl];
        }
    }

    // STS offsets packed 2 per u32
    u32 offsA, offsB;
    {
        u32 o[4];
#pragma unroll
        for (int j = 0; j < 4; ++j) {
            int l = t + NT * j;
            if (l < LSP) {
                int hh = l / HW;
                int ww = l - hh * HW;
                o[j] = (hh + 1) * SROW + (ww + 1);
            } else o[j] = 0;
        }
        offsA = o[0] | (o[1] << 16);
        offsB = o[2] | (o[3] << 16);
    }

    const u32* xg = g_xq + ((size_t)b * NCP + (size_t)cq * CPP) * LSP;
    u32 r[4];
#pragma unroll
    for (int j = 0; j < 3; ++j) r[j] = xg[t + NT * j];
    if (t < 112) r[3] = xg[t + NT * 3];

    u32 acc[4][7];
#pragma unroll
    for (int p = 0; p < 4; ++p)
#pragma unroll
        for (int j = 0; j < 7; ++j) acc[p][j] = 0u;

    const int cb = h * SROW + 7 * q;

    __syncthreads();

#pragma unroll 1
    for (int cpl = 0; cpl < CPP; ++cpl) {
        const int buf = cpl & 1;
        // store current channel-pair tile
        xs[buf][offsA & 0xFFFF] = r[0];
        xs[buf][offsA >> 16]    = r[1];
        xs[buf][offsB & 0xFFFF] = r[2];
        if (t < 112) xs[buf][offsB >> 16] = r[3];
        // prefetch next channel-pair
        if (cpl + 1 < CPP) {
            const u32* xn = xg + (size_t)(cpl + 1) * LSP;
#pragma unroll
            for (int j = 0; j < 3; ++j) r[j] = xn[t + NT * j];
            if (t < 112) r[3] = xn[t + NT * 3];
        }
        __syncthreads();

        const u32* wrow = ws + cpl * 72;
#pragma unroll
        for (int kh = 0; kh < 3; ++kh) {
            u32 xv[9];
#pragma unroll
            for (int i = 0; i < 9; ++i)
                xv[i] = xs[buf][cb + kh * SROW + i];
#pragma unroll
            for (int kw = 0; kw < 3; ++kw) {
                uint4 wv = *reinterpret_cast<const uint4*>(&wrow[(kh * 3 + kw) * 8 + g]);
#pragma unroll
                for (int j = 0; j < 7; ++j) {
                    sad2(acc[0][j], xv[j + kw], wv.x);
                    sad2(acc[1][j], xv[j + kw], wv.y);
                    sad2(acc[2][j], xv[j + kw], wv.z);
                    sad2(acc[3][j], xv[j + kw], wv.w);
                }
            }
        }
        __syncthreads();
    }

    // epilogue: dequantize, RED-accumulate negated partials (4 per output)
    const float INV = -1.0f / QS;
    float* ob = out + ((size_t)b * FOUT + fbase + g) * LSP + h * HW + 7 * q;
#pragma unroll
    for (int p = 0; p < 4; ++p) {
        float* o0 = ob + (size_t)p * LSP;
#pragma unroll
        for (int j = 0; j < 7; ++j)
            atomicAdd(&o0[j], (float)acc[p][j] * INV);
    }
}

extern "C" void kernel_launch(void* const* d_in, const int* in_sizes, int n_in,
                              void* d_out, int out_size) {
    const float* x = (const float*)d_in[0];
    const float* W = (const float*)d_in[1];
    if (n_in >= 2 && in_sizes[0] == FOUT * CIN * 9 && in_sizes[1] == BATCH * CIN * LSP) {
        const float* tmp = x; x = W; W = tmp;
    }
    float* out = (float*)d_out;

    prep_x_kernel<<<BATCH * NCP * LSP / 1024, 1024>>>(x);   // 784 blocks
    prep_w_kernel<<<NCP * 9 * FOUT / 256, 256>>>(W);        // 288 blocks
    zero_out_kernel<<<392, 1024>>>((float4*)out);

    dim3 grid(FOUT / 8, BATCH, NCHQ);   // 16 x 16 x 4 = 1024 CTAs
    adder2d_kernel<<<grid, NT>>>(out);
}

// round 11
// speedup vs baseline: 3.5677x; 3.5677x over previous
#include <cuda_runtime.h>
#include <cuda_fp16.h>
#include <cstdint>

// adder2d: out[b,f,l] = -sum_{c,kh,kw} |W[f,c,kh,kw] - xpad[b,c,...]|
// fp16x2 inner math (packed = 2 filters), fp32 promotion via gmem RED.
// PERSISTENT: 740 CTAs (148 SM x occ5), 2048 work units (8 fg x 16 b x 16 cq,
// CPC=8 channels) pulled from a global atomic counter (reset each replay).
// x and W pre-converted to fp16 by prep kernels: x duplicated (v,v) per elem,
// W packed per filter-pair. CTA 224 thr: t<112 -> pairs g..g+3 with g=0, else g=4.
// x tile dup fp16x2, double-buffered, row stride 36 u32 (conflict-free xv).

#define BATCH 16
#define CIN   128
#define HW    28
#define LSP   784
#define FOUT  128
#define NT    224
#define CPC   8
#define NCHQ  16
#define NFG   8            // filter groups (16 filters each)
#define NUNITS (NFG * BATCH * NCHQ)   // 2048
#define NCTA  740
#define SROW  36
#define TROWS 30
#define NFP   (FOUT / 2)   // 64 filter pairs

typedef unsigned int u32;

__device__ u32 g_xd[BATCH * CIN * LSP];   // dup fp16x2 of x: (h(v), h(v))
__device__ u32 g_wq[CIN * 9 * NFP];       // [(c*9+kk)][fp] = (h(W[2fp]), h(W[2fp+1]))
__device__ u32 g_unit;                    // work-stealing counter

// acc2 += | w2 - p2 |   (HFMA2 + LOP3 + HADD2 : 2 fma-pipe + 1 alu-pipe)
__device__ __forceinline__ void absdiff_acc(u32& acc, u32 p2, u32 negone, u32 w2) {
    asm("{\n\t"
        ".reg .b32 d;\n\t"
        "fma.rn.f16x2 d, %1, %2, %3;\n\t"
        "and.b32 d, d, 0x7FFF7FFF;\n\t"
        "add.rn.f16x2 %0, %0, d;\n\t"
        "}"
        : "+r"(acc) : "r"(p2), "r"(negone), "r"(w2));
}

__global__ void zero_out_kernel(float4* o) {
    if (blockIdx.x == 0 && threadIdx.x == 0) g_unit = 0;   // reset stealing counter
    o[(size_t)blockIdx.x * 1024 + threadIdx.x] = make_float4(0.f, 0.f, 0.f, 0.f);
}

__global__ void prep_x_kernel(const float* __restrict__ x) {
    int i = blockIdx.x * 1024 + threadIdx.x;   // over 16*128*784 = 1,605,632
    float v = x[i];
    __half2 hv = __floats2half2_rn(v, v);
    g_xd[i] = *reinterpret_cast<u32*>(&hv);
}

__global__ void prep_w_kernel(const float* __restrict__ Wt) {
    int i = blockIdx.x * 256 + threadIdx.x;    // over 128*9*64 = 73728
    if (i >= CIN * 9 * NFP) return;
    int fp = i & (NFP - 1);
    int ck = i >> 6;                           // c*9 + kk
    const float* wp = Wt + (size_t)(2 * fp) * (CIN * 9) + ck;
    __half2 hw = __floats2half2_rn(wp[0], wp[CIN * 9]);
    g_wq[(size_t)ck * NFP + fp] = *reinterpret_cast<u32*>(&hw);
}

__global__ __launch_bounds__(NT, 5)
void adder2d_kernel(float* __restrict__ out) {
    __shared__ u32 xs[2][TROWS * SROW];   // dup fp16x2 tiles, 8640 B
    __shared__ u32 ws[CPC * 9 * 8];       // [c*9+kk][pair0..7], 2304 B
    __shared__ u32 s_u;

    const int t  = threadIdx.x;
    const int tl = (t < 112) ? t : (t - 112);
    const int g  = (t < 112) ? 0 : 4;     // pair base within unit's 8 pairs
    const int h  = tl >> 2;
    const int q  = tl & 3;
    const int cb = h * SROW + 7 * q;
    const u32 NEG1 = 0xBC00BC00u;

    // one-time: zero both tiles (halo stays zero forever)
    for (int i = t; i < 2 * TROWS * SROW; i += NT)
        (&xs[0][0])[i] = 0u;

    // one-time: STS offsets packed 2 per u32
    u32 offsA, offsB;
    {
        u32 o[4];
#pragma unroll
        for (int j = 0; j < 4; ++j) {
            int l = t + NT * j;
            if (l < LSP) {
                int hh = l / HW;
                int ww = l - hh * HW;
                o[j] = (hh + 1) * SROW + (ww + 1);
            } else o[j] = 0;
        }
        offsA = o[0] | (o[1] << 16);
        offsB = o[2] | (o[3] << 16);
    }

    for (;;) {
        __syncthreads();                  // prior unit fully done (xs/ws reusable)
        if (t == 0) s_u = atomicAdd(&g_unit, 1u);
        __syncthreads();
        const u32 u = s_u;
        if (u >= NUNITS) break;

        const int fg = u & (NFG - 1);         // filter group (8 pairs)
        const int b  = (u >> 3) & (BATCH - 1);
        const int cq = u >> 7;                // channel chunk (8 ch)
        const int fp0 = fg * 8;

        // stage W: 8ch x 9kk x 8 pairs = 576 u32, coalesced from g_wq
        {
            const u32* wp = g_wq + (size_t)(cq * CPC * 9) * NFP + fp0;
            for (int i = t; i < CPC * 9 * 8; i += NT) {
                int p  = i & 7;
                int ck = i >> 3;
                ws[i] = wp[(size_t)ck * NFP + p];
            }
        }

        const u32* xg = g_xd + ((size_t)b * CIN + (size_t)cq * CPC) * LSP;
        u32 r[4];
#pragma unroll
        for (int j = 0; j < 3; ++j) r[j] = xg[t + NT * j];
        if (t < 112) r[3] = xg[t + NT * 3];

        u32 acc[4][7];
#pragma unroll
        for (int p = 0; p < 4; ++p)
#pragma unroll
            for (int j = 0; j < 7; ++j) acc[p][j] = 0u;

#pragma unroll 1
        for (int ch = 0; ch < CPC; ++ch) {
            const int buf = ch & 1;
            xs[buf][offsA & 0xFFFF] = r[0];
            xs[buf][offsA >> 16]    = r[1];
            xs[buf][offsB & 0xFFFF] = r[2];
            if (t < 112) xs[buf][offsB >> 16] = r[3];
            if (ch + 1 < CPC) {
                const u32* xn = xg + (size_t)(ch + 1) * LSP;
#pragma unroll
                for (int j = 0; j < 3; ++j) r[j] = xn[t + NT * j];
                if (t < 112) r[3] = xn[t + NT * 3];
            }
            __syncthreads();   // covers ws staging (ch==0) and this buf's STS

            const u32* wrow = ws + ch * 72;
#pragma unroll
            for (int kh = 0; kh < 3; ++kh) {
                u32 xv[9];
#pragma unroll
                for (int i = 0; i < 9; ++i)
                    xv[i] = xs[buf][cb + kh * SROW + i];
#pragma unroll
                for (int kw = 0; kw < 3; ++kw) {
                    uint4 wv = *reinterpret_cast<const uint4*>(
                        &wrow[(kh * 3 + kw) * 8 + g]);
#pragma unroll
                    for (int j = 0; j < 7; ++j) {
                        absdiff_acc(acc[0][j], xv[j + kw], NEG1, wv.x);
                        absdiff_acc(acc[1][j], xv[j + kw], NEG1, wv.y);
                        absdiff_acc(acc[2][j], xv[j + kw], NEG1, wv.z);
                        absdiff_acc(acc[3][j], xv[j + kw], NEG1, wv.w);
                    }
                }
            }
        }

        // epilogue: promote fp16x2 -> 2x fp32, RED-accumulate negated partials
        float* ob = out + ((size_t)b * FOUT + 2 * (fp0 + g)) * LSP + h * HW + 7 * q;
#pragma unroll
        for (int p = 0; p < 4; ++p) {
            float* o0 = ob + (size_t)(2 * p) * LSP;
            float* o1 = o0 + LSP;
#pragma unroll
            for (int j = 0; j < 7; ++j) {
                float2 v = __half22float2(*reinterpret_cast<__half2*>(&acc[p][j]));
                atomicAdd(&o0[j], -v.x);
                atomicAdd(&o1[j], -v.y);
            }
        }
    }
}

extern "C" void kernel_launch(void* const* d_in, const int* in_sizes, int n_in,
                              void* d_out, int out_size) {
    const float* x = (const float*)d_in[0];
    const float* W = (const float*)d_in[1];
    if (n_in >= 2 && in_sizes[0] == FOUT * CIN * 9 && in_sizes[1] == BATCH * CIN * LSP) {
        const float* tmp = x; x = W; W = tmp;
    }
    float* out = (float*)d_out;

    prep_x_kernel<<<BATCH * CIN * LSP / 1024, 1024>>>(x);   // 1568 blocks
    prep_w_kernel<<<(CIN * 9 * NFP + 255) / 256, 256>>>(W); // 288 blocks
    zero_out_kernel<<<392, 1024>>>((float4*)out);           // also resets counter

    adder2d_kernel<<<NCTA, NT>>>(out);
}